// round 1
// baseline (speedup 1.0000x reference)
#include <cuda_runtime.h>
#include <math.h>

#define BB 4
#define CC 512
#define NN 4096   // H*W = 64*64
#define DD 512

// Scratch: __device__ globals (no allocation allowed in kernel_launch)
__device__ float g_QKV[3][(size_t)BB * NN * DD];          // Q, K, V  (token-major: [b][t][d])
__device__ float g_S[(size_t)BB * NN * NN];               // attention matrix

#define SCALE 0.04419417382415922f   // 1/sqrt(512)

// ---------------------------------------------------------------------------
// QKV projection: out[b][t][d] = sum_c X[b][c][t] * W[d][c]
// X is x viewed as (B, C, N); W is (D, C) row-major.
// Tile: 64 (t) x 64 (d), k-chunk 16 over c. 256 threads, 4x4 micro-tile.
// ---------------------------------------------------------------------------
__global__ __launch_bounds__(256) void qkv_kernel(
    const float* __restrict__ x,
    const float* __restrict__ Wq,
    const float* __restrict__ Wk,
    const float* __restrict__ Wv)
{
    int b     = blockIdx.z / 3;
    int which = blockIdx.z % 3;
    const float* W = (which == 0) ? Wq : ((which == 1) ? Wk : Wv);
    float* out = &g_QKV[which][(size_t)b * NN * DD];
    const float* X = x + (size_t)b * CC * NN;

    __shared__ float Xs[16][64 + 1];  // [cc][tt]
    __shared__ float Ws[16][64 + 1];  // [cc][dd]

    int t0 = blockIdx.x * 64;
    int d0 = blockIdx.y * 64;
    int tid = threadIdx.x;
    int tx = tid % 16;   // d micro index
    int ty = tid / 16;   // t micro index

    float acc[4][4] = {};

    for (int c0 = 0; c0 < CC; c0 += 16) {
        // Xs[cc][tt] <- X[(c0+cc)*NN + t0+tt]   (contiguous in t)
        {
            int f  = tid * 4;
            int cc = f / 64;
            int tt = f % 64;
            float4 v = *(const float4*)&X[(size_t)(c0 + cc) * NN + t0 + tt];
            Xs[cc][tt + 0] = v.x; Xs[cc][tt + 1] = v.y;
            Xs[cc][tt + 2] = v.z; Xs[cc][tt + 3] = v.w;
        }
        // Ws[cc][dd] <- W[(d0+dd)*CC + c0+cc]   (contiguous in c)
        {
            int dd = tid / 4;
            int cc = (tid % 4) * 4;
            float4 v = *(const float4*)&W[(size_t)(d0 + dd) * CC + c0 + cc];
            Ws[cc + 0][dd] = v.x; Ws[cc + 1][dd] = v.y;
            Ws[cc + 2][dd] = v.z; Ws[cc + 3][dd] = v.w;
        }
        __syncthreads();

        #pragma unroll
        for (int kk = 0; kk < 16; kk++) {
            float a[4], w[4];
            #pragma unroll
            for (int u = 0; u < 4; u++) a[u] = Xs[kk][ty * 4 + u];
            #pragma unroll
            for (int v = 0; v < 4; v++) w[v] = Ws[kk][tx * 4 + v];
            #pragma unroll
            for (int u = 0; u < 4; u++)
                #pragma unroll
                for (int v = 0; v < 4; v++)
                    acc[u][v] += a[u] * w[v];
        }
        __syncthreads();
    }

    #pragma unroll
    for (int u = 0; u < 4; u++) {
        float4 r = make_float4(acc[u][0], acc[u][1], acc[u][2], acc[u][3]);
        *(float4*)&out[(size_t)(t0 + ty * 4 + u) * DD + d0 + tx * 4] = r;
    }
}

// ---------------------------------------------------------------------------
// S[b][i][j] = SCALE * sum_d Q[b][i][d] * K[b][j][d]
// Tile 64(i) x 64(j), k-chunk 16 over d.
// ---------------------------------------------------------------------------
__global__ __launch_bounds__(256) void s_kernel()
{
    int b = blockIdx.z;
    const float* Q = &g_QKV[0][(size_t)b * NN * DD];
    const float* K = &g_QKV[1][(size_t)b * NN * DD];
    float* S = g_S + (size_t)b * NN * NN;

    __shared__ float Qs[16][64 + 1];  // [kk][ii]
    __shared__ float Ks[16][64 + 1];  // [kk][jj]

    int i0 = blockIdx.x * 64;
    int j0 = blockIdx.y * 64;
    int tid = threadIdx.x;
    int tx = tid % 16;   // j micro
    int ty = tid / 16;   // i micro

    float acc[4][4] = {};

    for (int d0 = 0; d0 < DD; d0 += 16) {
        // Qs[kk][ii] <- Q[(i0+ii)*DD + d0+kk]  (contiguous over kk)
        {
            int ii = tid / 4;
            int kk = (tid % 4) * 4;
            float4 v = *(const float4*)&Q[(size_t)(i0 + ii) * DD + d0 + kk];
            Qs[kk + 0][ii] = v.x; Qs[kk + 1][ii] = v.y;
            Qs[kk + 2][ii] = v.z; Qs[kk + 3][ii] = v.w;
        }
        {
            int jj = tid / 4;
            int kk = (tid % 4) * 4;
            float4 v = *(const float4*)&K[(size_t)(j0 + jj) * DD + d0 + kk];
            Ks[kk + 0][jj] = v.x; Ks[kk + 1][jj] = v.y;
            Ks[kk + 2][jj] = v.z; Ks[kk + 3][jj] = v.w;
        }
        __syncthreads();

        #pragma unroll
        for (int kk = 0; kk < 16; kk++) {
            float a[4], c[4];
            #pragma unroll
            for (int u = 0; u < 4; u++) a[u] = Qs[kk][ty * 4 + u];
            #pragma unroll
            for (int v = 0; v < 4; v++) c[v] = Ks[kk][tx * 4 + v];
            #pragma unroll
            for (int u = 0; u < 4; u++)
                #pragma unroll
                for (int v = 0; v < 4; v++)
                    acc[u][v] += a[u] * c[v];
        }
        __syncthreads();
    }

    #pragma unroll
    for (int u = 0; u < 4; u++) {
        float4 r = make_float4(acc[u][0] * SCALE, acc[u][1] * SCALE,
                               acc[u][2] * SCALE, acc[u][3] * SCALE);
        *(float4*)&S[(size_t)(i0 + ty * 4 + u) * NN + j0 + tx * 4] = r;
    }
}

// ---------------------------------------------------------------------------
// In-place row softmax over S. One block per row (N=4096, 256 thr, 16/thread).
// ---------------------------------------------------------------------------
__global__ __launch_bounds__(256) void softmax_kernel()
{
    __shared__ float red[256];
    size_t base = ((size_t)blockIdx.y * NN + blockIdx.x) * NN;
    float* row = g_S + base;
    int t = threadIdx.x;

    float vals[16];
    float m = -1e30f;
    #pragma unroll
    for (int u = 0; u < 16; u++) {
        vals[u] = row[t + u * 256];
        m = fmaxf(m, vals[u]);
    }
    red[t] = m;
    __syncthreads();
    for (int s = 128; s > 0; s >>= 1) {
        if (t < s) red[t] = fmaxf(red[t], red[t + s]);
        __syncthreads();
    }
    m = red[0];
    __syncthreads();

    float sum = 0.f;
    #pragma unroll
    for (int u = 0; u < 16; u++) {
        vals[u] = __expf(vals[u] - m);
        sum += vals[u];
    }
    red[t] = sum;
    __syncthreads();
    for (int s = 128; s > 0; s >>= 1) {
        if (t < s) red[t] += red[t + s];
        __syncthreads();
    }
    float inv = 1.0f / red[0];
    #pragma unroll
    for (int u = 0; u < 16; u++)
        row[t + u * 256] = vals[u] * inv;
}

// ---------------------------------------------------------------------------
// scores_out[b][j] = sum_i S[b][i][j]   (column sums, coalesced over j)
// ---------------------------------------------------------------------------
__global__ __launch_bounds__(256) void colsum_kernel(float* __restrict__ scores_out)
{
    int b = blockIdx.y;
    int j = blockIdx.x * 256 + threadIdx.x;
    const float* Sb = g_S + (size_t)b * NN * NN;
    float s = 0.f;
    for (int i = 0; i < NN; i++)
        s += Sb[(size_t)i * NN + j];
    scores_out[(size_t)b * NN + j] = s;
}

// ---------------------------------------------------------------------------
// Final output (d-major): out[b][d][t] = sum_j S[b][t][j] * V[b][j][d]
// Tile 64(t) x 64(d), k-chunk 16 over j.
// ---------------------------------------------------------------------------
__global__ __launch_bounds__(256) void o_kernel(float* __restrict__ out)
{
    int b = blockIdx.z;
    const float* S = g_S + (size_t)b * NN * NN;
    const float* V = &g_QKV[2][(size_t)b * NN * DD];
    float* O = out + (size_t)b * DD * NN;

    __shared__ float Ss[16][64 + 1];  // [kk(j)][tt]
    __shared__ float Vs[16][64 + 1];  // [kk(j)][dd]

    int t0 = blockIdx.x * 64;
    int d0 = blockIdx.y * 64;
    int tid = threadIdx.x;
    int tx = tid % 16;   // d micro
    int ty = tid / 16;   // t micro

    float acc[4][4] = {};   // [t][d]

    for (int j0 = 0; j0 < NN; j0 += 16) {
        // Ss[kk][tt] <- S[(t0+tt)*NN + j0+kk]  (contiguous over kk)
        {
            int tt = tid / 4;
            int kk = (tid % 4) * 4;
            float4 v = *(const float4*)&S[(size_t)(t0 + tt) * NN + j0 + kk];
            Ss[kk + 0][tt] = v.x; Ss[kk + 1][tt] = v.y;
            Ss[kk + 2][tt] = v.z; Ss[kk + 3][tt] = v.w;
        }
        // Vs[kk][dd] <- V[(j0+kk)*DD + d0+dd]  (contiguous over dd)
        {
            int f  = tid * 4;
            int kk = f / 64;
            int dd = f % 64;
            float4 v = *(const float4*)&V[(size_t)(j0 + kk) * DD + d0 + dd];
            Vs[kk][dd + 0] = v.x; Vs[kk][dd + 1] = v.y;
            Vs[kk][dd + 2] = v.z; Vs[kk][dd + 3] = v.w;
        }
        __syncthreads();

        #pragma unroll
        for (int kk = 0; kk < 16; kk++) {
            float a[4], c[4];
            #pragma unroll
            for (int u = 0; u < 4; u++) a[u] = Ss[kk][ty * 4 + u];
            #pragma unroll
            for (int v = 0; v < 4; v++) c[v] = Vs[kk][tx * 4 + v];
            #pragma unroll
            for (int u = 0; u < 4; u++)
                #pragma unroll
                for (int v = 0; v < 4; v++)
                    acc[u][v] += a[u] * c[v];
        }
        __syncthreads();
    }

    // O[(d0+dd)*NN + t0+tt] ; contiguous over tt -> vectorize over u
    #pragma unroll
    for (int v = 0; v < 4; v++) {
        float4 r = make_float4(acc[0][v], acc[1][v], acc[2][v], acc[3][v]);
        *(float4*)&O[(size_t)(d0 + tx * 4 + v) * NN + t0 + ty * 4] = r;
    }
}

// ---------------------------------------------------------------------------
extern "C" void kernel_launch(void* const* d_in, const int* in_sizes, int n_in,
                              void* d_out, int out_size)
{
    const float* x  = (const float*)d_in[0];
    const float* Wk = (const float*)d_in[1];
    const float* Wq = (const float*)d_in[2];
    const float* Wv = (const float*)d_in[3];

    float* out        = (float*)d_out;                       // (B, D, H, W)
    float* scores_out = out + (size_t)BB * DD * NN;          // (B, 1, H, W)

    qkv_kernel<<<dim3(NN / 64, DD / 64, BB * 3), 256>>>(x, Wq, Wk, Wv);
    s_kernel<<<dim3(NN / 64, NN / 64, BB), 256>>>();
    softmax_kernel<<<dim3(NN, BB), 256>>>();
    o_kernel<<<dim3(NN / 64, DD / 64, BB), 256>>>(out);
    colsum_kernel<<<dim3(NN / 256, BB), 256>>>(scores_out);
}